// round 12
// baseline (speedup 1.0000x reference)
#include <cuda_runtime.h>
#include <cuda_fp16.h>
#include <math.h>
#include <cstdint>

#define BB 8
#define LL 1024
#define DD 1024
#define HH 16
#define DK 64
#define ROWS_TOT (BB*LL)          // 8192

// Scratch (device globals)
__device__ __half g_qh [(size_t)ROWS_TOT * DD];   // fp16 q heads (scaled 1/8)
__device__ __half g_kh [(size_t)ROWS_TOT * DD];   // fp16 k heads
__device__ __half g_vhT[(size_t)ROWS_TOT * DD];   // [b][h][d][token] fp16
__device__ __half g_ctx[(size_t)ROWS_TOT * DD];   // fp16
__device__ float  g_proj[(size_t)ROWS_TOT * DD];
__device__ __half g_as [(size_t)ROWS_TOT * DD];
__device__ __half g_ws [(size_t)DD * DD];

// ---------------------------------------------------------------------------
// helpers
// ---------------------------------------------------------------------------
__device__ __forceinline__ uint32_t smem_u32(const void* p) {
    uint32_t a;
    asm("{ .reg .u64 t; cvta.to.shared.u64 t, %1; cvt.u32.u64 %0, t; }" : "=r"(a) : "l"(p));
    return a;
}
__device__ __forceinline__ void cp16(uint32_t dst, const void* src) {
    asm volatile("cp.async.cg.shared.global [%0], [%1], 16;" :: "r"(dst), "l"(src));
}
#define CP_COMMIT asm volatile("cp.async.commit_group;" ::: "memory")
#define CP_WAIT2  asm volatile("cp.async.wait_group 2;" ::: "memory")
#define CP_WAIT1  asm volatile("cp.async.wait_group 1;" ::: "memory")
#define CP_WAIT0  asm volatile("cp.async.wait_group 0;" ::: "memory")

__device__ __forceinline__ void mma_f16(float* c, const uint32_t* a, const uint32_t* b) {
    asm volatile(
        "mma.sync.aligned.m16n8k16.row.col.f32.f16.f16.f32 "
        "{%0,%1,%2,%3},{%4,%5,%6,%7},{%8,%9},{%0,%1,%2,%3};"
        : "+f"(c[0]), "+f"(c[1]), "+f"(c[2]), "+f"(c[3])
        : "r"(a[0]), "r"(a[1]), "r"(a[2]), "r"(a[3]), "r"(b[0]), "r"(b[1]));
}
__device__ __forceinline__ void ldsm4(uint32_t& r0, uint32_t& r1, uint32_t& r2,
                                      uint32_t& r3, uint32_t addr) {
    asm volatile("ldmatrix.sync.aligned.m8n8.x4.shared.b16 {%0,%1,%2,%3}, [%4];"
                 : "=r"(r0), "=r"(r1), "=r"(r2), "=r"(r3) : "r"(addr));
}
__device__ __forceinline__ void ldsm2(uint32_t& r0, uint32_t& r1, uint32_t addr) {
    asm volatile("ldmatrix.sync.aligned.m8n8.x2.shared.b16 {%0,%1}, [%2];"
                 : "=r"(r0), "=r"(r1) : "r"(addr));
}

// f32 -> fp16 convert
__global__ __launch_bounds__(256) void conv_f16(
    const float* __restrict__ x, __half* __restrict__ hi, int n4)
{
    int i = blockIdx.x * blockDim.x + threadIdx.x;
    if (i >= n4) return;
    float4 v = ((const float4*)x)[i];
    ((__half2*)hi)[i * 2]     = __floats2half2_rn(v.x, v.y);
    ((__half2*)hi)[i * 2 + 1] = __floats2half2_rn(v.z, v.w);
}

// ===========================================================================
// single-term fp16 GEMM (ldmatrix fragments). Output modes:
//   outT: transposed fp16 (V proj -> vhT) | outH: planar fp16 (Q/K) | outF: fp32
// 128x128 tile, BK=32, 512 threads
// ===========================================================================
#define PL_E 5120
#define PL_B (PL_E*2)
#define BUF1_B (2*PL_B)
#define GEMM1_SMEM (2*BUF1_B)

__global__ __launch_bounds__(512) void gemm_f16_1t(
    const __half* __restrict__ A, const __half* __restrict__ B,
    const float* __restrict__ bias, const float* __restrict__ npm, float scale,
    float* __restrict__ outF, __half* __restrict__ outH, __half* __restrict__ outT)
{
    extern __shared__ char sm[];
    const uint32_t smb = smem_u32(sm);
    const int tid = threadIdx.x, wid = tid >> 5, lane = tid & 31;
    const int g = lane >> 2, tg = lane & 3;
    const int bm = blockIdx.y * 128, bn = blockIdx.x * 128;
    const int wm = (wid & 1) * 64, wn = (wid >> 1) * 16;
    const int lrow = lane & 15, lkh = (lane >> 4) * 16;

    const __half* srcs[2] = { A + (size_t)bm * DD, B + (size_t)bn * DD };
    const int frow = tid >> 2, fc = tid & 3;

    float acc[4][2][4];
#pragma unroll
    for (int mi = 0; mi < 4; mi++)
#pragma unroll
        for (int ni = 0; ni < 2; ni++)
#pragma unroll
            for (int r = 0; r < 4; r++) acc[mi][ni][r] = 0.f;

#pragma unroll
    for (int i = 0; i < 2; i++)
        cp16(smb + i * PL_B + frow * 80 + fc * 16, srcs[i] + (size_t)frow * DD + fc * 8);
    CP_COMMIT;

    for (int kt = 0; kt < 32; kt++) {
        if (kt < 31) {
#pragma unroll
            for (int i = 0; i < 2; i++)
                cp16(smb + ((kt + 1) & 1) * BUF1_B + i * PL_B + frow * 80 + fc * 16,
                     srcs[i] + (size_t)frow * DD + (kt + 1) * 32 + fc * 8);
            CP_COMMIT;
            CP_WAIT1;
        } else {
            CP_WAIT0;
        }
        __syncthreads();

        const uint32_t bufb = smb + (kt & 1) * BUF1_B;
#pragma unroll
        for (int ks = 0; ks < 2; ks++) {
            uint32_t a_h[4][4], b4[4], b_h[2][2];
#pragma unroll
            for (int mi = 0; mi < 4; mi++)
                ldsm4(a_h[mi][0], a_h[mi][1], a_h[mi][2], a_h[mi][3],
                      bufb + (wm + mi * 16 + lrow) * 80 + ks * 32 + lkh);
            ldsm4(b4[0], b4[1], b4[2], b4[3],
                  bufb + PL_B + (wn + lrow) * 80 + ks * 32 + lkh);
            b_h[0][0] = b4[0]; b_h[0][1] = b4[2];
            b_h[1][0] = b4[1]; b_h[1][1] = b4[3];
#pragma unroll
            for (int mi = 0; mi < 4; mi++)
#pragma unroll
                for (int ni = 0; ni < 2; ni++)
                    mma_f16(acc[mi][ni], a_h[mi], b_h[ni]);
        }
        __syncthreads();
    }

    if (outT) {
        __half* smT = (__half*)sm;
#pragma unroll
        for (int mi = 0; mi < 4; mi++) {
            int r = wm + mi * 16 + g;
            float nv0 = npm[bm + r] * scale, nv1 = npm[bm + r + 8] * scale;
#pragma unroll
            for (int ni = 0; ni < 2; ni++) {
                int c = wn + ni * 8 + 2 * tg;
                float b0 = bias[bn + c], b1 = bias[bn + c + 1];
                smT[c * 136 + r]           = __float2half((acc[mi][ni][0] + b0) * nv0);
                smT[(c + 1) * 136 + r]     = __float2half((acc[mi][ni][1] + b1) * nv0);
                smT[c * 136 + r + 8]       = __float2half((acc[mi][ni][2] + b0) * nv1);
                smT[(c + 1) * 136 + r + 8] = __float2half((acc[mi][ni][3] + b1) * nv1);
            }
        }
        __syncthreads();
        const int b = bm >> 10, token0 = bm & 1023;
#pragma unroll
        for (int p = 0; p < 4; p++) {
            int cr = (tid >> 4) + p * 32;
            int unit = tid & 15;
            int C = bn + cr;
            int h = C >> 6, d = C & 63;
            size_t dst = ((size_t)(b * 16 + h) * 64 + d) * 1024 + token0 + unit * 8;
            *(uint4*)&outT[dst] = *(const uint4*)&smT[cr * 136 + unit * 8];
        }
    } else if (outH) {
#pragma unroll
        for (int mi = 0; mi < 4; mi++) {
            int r0 = bm + wm + mi * 16 + g, r1 = r0 + 8;
            float nv0 = npm[r0] * scale, nv1 = npm[r1] * scale;
#pragma unroll
            for (int ni = 0; ni < 2; ni++) {
                int c0 = bn + wn + ni * 8 + 2 * tg;
                float b0 = bias[c0], b1 = bias[c0 + 1];
                *(__half2*)&outH[(size_t)r0 * DD + c0] =
                    __floats2half2_rn((acc[mi][ni][0] + b0) * nv0, (acc[mi][ni][1] + b1) * nv0);
                *(__half2*)&outH[(size_t)r1 * DD + c0] =
                    __floats2half2_rn((acc[mi][ni][2] + b0) * nv1, (acc[mi][ni][3] + b1) * nv1);
            }
        }
    } else {
#pragma unroll
        for (int mi = 0; mi < 4; mi++) {
            int r0 = bm + wm + mi * 16 + g, r1 = r0 + 8;
            float nv0 = npm[r0] * scale, nv1 = npm[r1] * scale;
#pragma unroll
            for (int ni = 0; ni < 2; ni++) {
                int c0 = bn + wn + ni * 8 + 2 * tg;
                float b0 = bias[c0], b1 = bias[c0 + 1];
                *(float2*)&outF[(size_t)r0 * DD + c0] =
                    make_float2((acc[mi][ni][0] + b0) * nv0, (acc[mi][ni][1] + b1) * nv0);
                *(float2*)&outF[(size_t)r1 * DD + c0] =
                    make_float2((acc[mi][ni][2] + b0) * nv1, (acc[mi][ni][3] + b1) * nv1);
            }
        }
    }
}

// ===========================================================================
// Fused attention, register-resident scores.
// block = (b,h) x 32 q-rows, 512 threads (16 warps: 2 wq x 8 wk)
// S accumulated in regs (64 f32/thread) -> mask (direct gmem int2) ->
// register softmax (quad shfl + 32x8 smem reduce) -> P fp16 smem (only store)
// -> coalesced attn write from P -> PV fp16 mma (V^T quad-buffered).
// smem: P 32x2096=67072 @0 | red 1KB @67072 | Q 4608 @68096 | K/VT 4x18432 @72704
// ===========================================================================
#define POFF 0
#define PSTRB 2096
#define REDOFF 67072
#define QOFF 68096
#define KOFF 72704
#define KBUF 18432
#define VTBUF 17408
#define VTSTRB 272
#define ATT_SMEM (KOFF + 4*KBUF)      // 146432

__global__ __launch_bounds__(512) void attn_kernel(
    const __half* __restrict__ qh, const __half* __restrict__ kh,
    const __half* __restrict__ vhT, const int* __restrict__ mask,
    float* __restrict__ attn, __half* __restrict__ ctx)
{
    extern __shared__ char sm[];
    const uint32_t smb = smem_u32(sm);
    float* red = (float*)(sm + REDOFF);       // [32][8]

    const int tid = threadIdx.x, wid = tid >> 5, lane = tid & 31;
    const int g = lane >> 2, tg = lane & 3;
    const int lrow = lane & 15, lkh = (lane >> 4) * 16;
    const int bh = blockIdx.x;
    const int b = bh >> 4, h = bh & 15;
    const int q0 = blockIdx.y * 32;
    const int wq = wid & 1;
    const int wk = wid >> 1;

    const __half* qp_g = qh + ((size_t)b * LL + q0) * DD + h * DK;
    const __half* kp_g = kh + (size_t)b * LL * DD + h * DK;
    const __half* vTp = vhT + (size_t)bh * DK * LL;
    float* attnBase = attn + ((size_t)bh * LL + q0) * LL;
    const int row0 = wq * 16 + g;             // local row (and row0+8)
    const int* mr0 = mask + ((size_t)b * LL + q0 + row0) * LL;
    const int* mr1 = mr0 + 8 * LL;

    // Q load + K0 (group 1), K1 (group 2)
    if (tid < 256) {
        int row = tid >> 3, c8 = tid & 7;
        cp16(smb + QOFF + row * 144 + c8 * 16, qp_g + (size_t)row * DD + c8 * 8);
    }
#pragma unroll
    for (int j = 0; j < 2; j++) {
        int idx = tid + 512 * j;
        int row = idx >> 3, c8 = idx & 7;
        cp16(smb + KOFF + row * 144 + c8 * 16, kp_g + (size_t)row * DD + c8 * 8);
    }
    CP_COMMIT;
#pragma unroll
    for (int j = 0; j < 2; j++) {
        int idx = tid + 512 * j;
        int row = idx >> 3, c8 = idx & 7;
        cp16(smb + KOFF + KBUF + row * 144 + c8 * 16,
             kp_g + (size_t)(128 + row) * DD + c8 * 8);
    }
    CP_COMMIT;

    // ---- S = Q K^T, scores stay in registers; mask folded per chunk ----
    float sacc[8][2][4];
    for (int kc = 0; kc < 8; kc++) {
        if (kc < 6) {
#pragma unroll
            for (int j = 0; j < 2; j++) {
                int idx = tid + 512 * j;
                int row = idx >> 3, c8 = idx & 7;
                cp16(smb + KOFF + ((kc + 2) & 3) * KBUF + row * 144 + c8 * 16,
                     kp_g + (size_t)((kc + 2) * 128 + row) * DD + c8 * 8);
            }
            CP_COMMIT;
            CP_WAIT2;
        } else if (kc == 6) {
            CP_WAIT1;
        } else {
            CP_WAIT0;
        }
        __syncthreads();

        const uint32_t kb = smb + KOFF + (kc & 3) * KBUF;
#pragma unroll
        for (int ni = 0; ni < 2; ni++)
#pragma unroll
            for (int r = 0; r < 4; r++) sacc[kc][ni][r] = 0.f;

#pragma unroll
        for (int ks = 0; ks < 4; ks++) {
            uint32_t a_h[4], b4[4], b_h[2][2];
            ldsm4(a_h[0], a_h[1], a_h[2], a_h[3],
                  smb + QOFF + (wq * 16 + lrow) * 144 + ks * 32 + lkh);
            ldsm4(b4[0], b4[1], b4[2], b4[3],
                  kb + (wk * 16 + lrow) * 144 + ks * 32 + lkh);
            b_h[0][0] = b4[0]; b_h[0][1] = b4[2];
            b_h[1][0] = b4[1]; b_h[1][1] = b4[3];
            mma_f16(sacc[kc][0], a_h, b_h[0]);
            mma_f16(sacc[kc][1], a_h, b_h[1]);
        }
        // fold mask for this chunk (each 8B segment owned by exactly one thread)
#pragma unroll
        for (int ni = 0; ni < 2; ni++) {
            int c = kc * 128 + wk * 16 + ni * 8 + 2 * tg;
            int2 m0 = *(const int2*)&mr0[c];
            int2 m1 = *(const int2*)&mr1[c];
            if (m0.x) sacc[kc][ni][0] = -1e30f;
            if (m0.y) sacc[kc][ni][1] = -1e30f;
            if (m1.x) sacc[kc][ni][2] = -1e30f;
            if (m1.y) sacc[kc][ni][3] = -1e30f;
        }
    }

    // ---- register softmax ----
    float mx0 = -1e30f, mx1 = -1e30f;
#pragma unroll
    for (int kc = 0; kc < 8; kc++)
#pragma unroll
        for (int ni = 0; ni < 2; ni++) {
            mx0 = fmaxf(mx0, fmaxf(sacc[kc][ni][0], sacc[kc][ni][1]));
            mx1 = fmaxf(mx1, fmaxf(sacc[kc][ni][2], sacc[kc][ni][3]));
        }
    mx0 = fmaxf(mx0, __shfl_xor_sync(0xffffffffu, mx0, 1));
    mx0 = fmaxf(mx0, __shfl_xor_sync(0xffffffffu, mx0, 2));
    mx1 = fmaxf(mx1, __shfl_xor_sync(0xffffffffu, mx1, 1));
    mx1 = fmaxf(mx1, __shfl_xor_sync(0xffffffffu, mx1, 2));
    __syncthreads();                    // K-phase readers done before red reuse
    if (tg == 0) {
        red[row0 * 8 + wk] = mx0;
        red[(row0 + 8) * 8 + wk] = mx1;
    }
    __syncthreads();
    float m0 = -1e30f, m1 = -1e30f;
#pragma unroll
    for (int w = 0; w < 8; w++) {
        m0 = fmaxf(m0, red[row0 * 8 + w]);
        m1 = fmaxf(m1, red[(row0 + 8) * 8 + w]);
    }

    float sm0 = 0.f, sm1 = 0.f;
#pragma unroll
    for (int kc = 0; kc < 8; kc++)
#pragma unroll
        for (int ni = 0; ni < 2; ni++) {
            float e0 = (sacc[kc][ni][0] <= -9e29f) ? 0.f : __expf(sacc[kc][ni][0] - m0);
            float e1 = (sacc[kc][ni][1] <= -9e29f) ? 0.f : __expf(sacc[kc][ni][1] - m0);
            float e2 = (sacc[kc][ni][2] <= -9e29f) ? 0.f : __expf(sacc[kc][ni][2] - m1);
            float e3 = (sacc[kc][ni][3] <= -9e29f) ? 0.f : __expf(sacc[kc][ni][3] - m1);
            sacc[kc][ni][0] = e0; sacc[kc][ni][1] = e1;
            sacc[kc][ni][2] = e2; sacc[kc][ni][3] = e3;
            sm0 += e0 + e1;
            sm1 += e2 + e3;
        }
    sm0 += __shfl_xor_sync(0xffffffffu, sm0, 1);
    sm0 += __shfl_xor_sync(0xffffffffu, sm0, 2);
    sm1 += __shfl_xor_sync(0xffffffffu, sm1, 1);
    sm1 += __shfl_xor_sync(0xffffffffu, sm1, 2);
    __syncthreads();
    if (tg == 0) {
        red[row0 * 8 + wk] = sm0;
        red[(row0 + 8) * 8 + wk] = sm1;
    }
    __syncthreads();
    float s0 = 0.f, s1 = 0.f;
#pragma unroll
    for (int w = 0; w < 8; w++) {
        s0 += red[row0 * 8 + w];
        s1 += red[(row0 + 8) * 8 + w];
    }
    float inv0 = 1.f / s0, inv1 = 1.f / s1;

    // ---- write P fp16 to smem (only score store) ----
#pragma unroll
    for (int kc = 0; kc < 8; kc++)
#pragma unroll
        for (int ni = 0; ni < 2; ni++) {
            int c = kc * 128 + wk * 16 + ni * 8 + 2 * tg;
            *(__half2*)(sm + POFF + row0 * PSTRB + c * 2) =
                __floats2half2_rn(sacc[kc][ni][0] * inv0, sacc[kc][ni][1] * inv0);
            *(__half2*)(sm + POFF + (row0 + 8) * PSTRB + c * 2) =
                __floats2half2_rn(sacc[kc][ni][2] * inv1, sacc[kc][ni][3] * inv1);
        }
    __syncthreads();

    // prefetch V^T chunks 0,1 (overlap with attn write)
#pragma unroll
    for (int j = 0; j < 2; j++) {
        int idx = tid + 512 * j;
        int d = idx >> 4, tk = idx & 15;
        cp16(smb + KOFF + d * VTSTRB + tk * 16, vTp + (size_t)d * LL + tk * 8);
    }
    CP_COMMIT;
#pragma unroll
    for (int j = 0; j < 2; j++) {
        int idx = tid + 512 * j;
        int d = idx >> 4, tk = idx & 15;
        cp16(smb + KOFF + VTBUF + d * VTSTRB + tk * 16,
             vTp + (size_t)d * LL + 128 + tk * 8);
    }
    CP_COMMIT;

    // ---- coalesced attn write from P ----
#pragma unroll
    for (int rr = 0; rr < 2; rr++) {
        int r = wid * 2 + rr;
        const __half2* Pr = (const __half2*)(sm + POFF + r * PSTRB);
        float* dst = attnBase + (size_t)r * LL;
#pragma unroll
        for (int c2 = lane; c2 < 512; c2 += 32) {
            float2 p2 = __half22float2(Pr[c2]);
            *(float2*)&dst[c2 * 2] = p2;
        }
    }

    // ---- PV: fp16 mma, warp tile 16q x 8d, quad-buffered V^T ----
    float pacc[4] = {0.f, 0.f, 0.f, 0.f};
    for (int vc = 0; vc < 8; vc++) {
        if (vc < 6) {
#pragma unroll
            for (int j = 0; j < 2; j++) {
                int idx = tid + 512 * j;
                int d = idx >> 4, tk = idx & 15;
                cp16(smb + KOFF + ((vc + 2) & 3) * VTBUF + d * VTSTRB + tk * 16,
                     vTp + (size_t)d * LL + (vc + 2) * 128 + tk * 8);
            }
            CP_COMMIT;
            CP_WAIT2;
        } else if (vc == 6) {
            CP_WAIT1;
        } else {
            CP_WAIT0;
        }
        __syncthreads();

        const uint32_t vtb = smb + KOFF + (vc & 3) * VTBUF;
        const uint32_t pb = smb + POFF + (wq * 16) * PSTRB + vc * 256;
#pragma unroll
        for (int kk = 0; kk < 8; kk++) {
            uint32_t a[4], bfr[2];
            ldsm4(a[0], a[1], a[2], a[3], pb + lrow * PSTRB + kk * 32 + lkh);
            ldsm2(bfr[0], bfr[1],
                  vtb + (wk * 8 + (lane & 7)) * VTSTRB + kk * 32 + ((lane >> 3) & 1) * 16);
            mma_f16(pacc, a, bfr);
        }
    }

    {
        int c = h * DK + wk * 8 + 2 * tg;
        size_t r0 = (size_t)b * LL + q0 + wq * 16 + g;
        *(__half2*)&ctx[r0 * DD + c]       = __floats2half2_rn(pacc[0], pacc[1]);
        *(__half2*)&ctx[(r0 + 8) * DD + c] = __floats2half2_rn(pacc[2], pacc[3]);
    }
}

// ---------------------------------------------------------------------------
// LayerNorm(proj + residual) * g + b
// ---------------------------------------------------------------------------
__global__ __launch_bounds__(256) void ln_kernel(
    const float* __restrict__ proj, const float* __restrict__ resid,
    const float* __restrict__ gam, const float* __restrict__ bet,
    float* __restrict__ out)
{
    __shared__ float red[8];
    const int row = blockIdx.x;
    const int tid = threadIdx.x;
    const int c0 = tid * 4;
    const int lane = tid & 31, wid = tid >> 5;

    float4 pv = *(const float4*)(proj + (size_t)row * DD + c0);
    float4 rv = *(const float4*)(resid + (size_t)row * DD + c0);
    float x0 = pv.x + rv.x, x1 = pv.y + rv.y, x2 = pv.z + rv.z, x3 = pv.w + rv.w;

    float s = x0 + x1 + x2 + x3;
#pragma unroll
    for (int o = 16; o; o >>= 1) s += __shfl_xor_sync(0xffffffffu, s, o);
    if (lane == 0) red[wid] = s;
    __syncthreads();
    float tot = (lane < 8) ? red[lane] : 0.f;
#pragma unroll
    for (int o = 4; o; o >>= 1) tot += __shfl_xor_sync(0xffffffffu, tot, o);
    tot = __shfl_sync(0xffffffffu, tot, 0);
    float mean = tot * (1.f / 1024.f);

    float d0 = x0 - mean, d1 = x1 - mean, d2 = x2 - mean, d3 = x3 - mean;
    float sq = d0 * d0 + d1 * d1 + d2 * d2 + d3 * d3;
#pragma unroll
    for (int o = 16; o; o >>= 1) sq += __shfl_xor_sync(0xffffffffu, sq, o);
    __syncthreads();
    if (lane == 0) red[wid] = sq;
    __syncthreads();
    float tot2 = (lane < 8) ? red[lane] : 0.f;
#pragma unroll
    for (int o = 4; o; o >>= 1) tot2 += __shfl_xor_sync(0xffffffffu, tot2, o);
    tot2 = __shfl_sync(0xffffffffu, tot2, 0);
    float k = rsqrtf(tot2 * (1.f / 1024.f) + 1e-5f);

    float4 gv = *(const float4*)(gam + c0);
    float4 bv = *(const float4*)(bet + c0);
    float4 ov;
    ov.x = d0 * k * gv.x + bv.x;
    ov.y = d1 * k * gv.y + bv.y;
    ov.z = d2 * k * gv.z + bv.z;
    ov.w = d3 * k * gv.w + bv.w;
    *(float4*)&out[(size_t)row * DD + c0] = ov;
}

// ---------------------------------------------------------------------------
extern "C" void kernel_launch(void* const* d_in, const int* in_sizes, int n_in,
                              void* d_out, int out_size)
{
    const float* q    = (const float*)d_in[0];
    const float* k    = (const float*)d_in[1];
    const float* v    = (const float*)d_in[2];
    const int*   mask = (const int*)  d_in[3];
    const float* npm  = (const float*)d_in[4];
    const float* Wq   = (const float*)d_in[5];
    const float* bq   = (const float*)d_in[6];
    const float* Wk   = (const float*)d_in[7];
    const float* bk   = (const float*)d_in[8];
    const float* Wv   = (const float*)d_in[9];
    const float* bv   = (const float*)d_in[10];
    const float* Wf   = (const float*)d_in[11];
    const float* bf   = (const float*)d_in[12];
    const float* ln_g = (const float*)d_in[13];
    const float* ln_b = (const float*)d_in[14];

    float* out  = (float*)d_out;
    float* attn = out + (size_t)BB * LL * DD;

    __half *qh, *kh, *vhT, *ctx, *as, *ws;
    float *proj;
    cudaGetSymbolAddress((void**)&qh,  g_qh);
    cudaGetSymbolAddress((void**)&kh,  g_kh);
    cudaGetSymbolAddress((void**)&vhT, g_vhT);
    cudaGetSymbolAddress((void**)&ctx, g_ctx);
    cudaGetSymbolAddress((void**)&proj, g_proj);
    cudaGetSymbolAddress((void**)&as,  g_as);
    cudaGetSymbolAddress((void**)&ws,  g_ws);

    cudaFuncSetAttribute(gemm_f16_1t, cudaFuncAttributeMaxDynamicSharedMemorySize, GEMM1_SMEM);
    cudaFuncSetAttribute(attn_kernel, cudaFuncAttributeMaxDynamicSharedMemorySize, ATT_SMEM);

    const int nA4 = ROWS_TOT * DD / 4;
    const int nW4 = DD * DD / 4;
    dim3 gG(DD / 128, ROWS_TOT / 128);   // (8, 64)

    // Q projection (scale 1/8 folded) -> fp16
    conv_f16<<<(nA4 + 255) / 256, 256>>>(q, as, nA4);
    conv_f16<<<(nW4 + 255) / 256, 256>>>(Wq, ws, nW4);
    gemm_f16_1t<<<gG, 512, GEMM1_SMEM>>>(as, ws, bq, npm, 0.125f, nullptr, qh, nullptr);
    // K projection -> fp16
    conv_f16<<<(nA4 + 255) / 256, 256>>>(k, as, nA4);
    conv_f16<<<(nW4 + 255) / 256, 256>>>(Wk, ws, nW4);
    gemm_f16_1t<<<gG, 512, GEMM1_SMEM>>>(as, ws, bk, npm, 1.0f, nullptr, kh, nullptr);
    // V projection -> transposed fp16 vhT
    conv_f16<<<(nA4 + 255) / 256, 256>>>(v, as, nA4);
    conv_f16<<<(nW4 + 255) / 256, 256>>>(Wv, ws, nW4);
    gemm_f16_1t<<<gG, 512, GEMM1_SMEM>>>(as, ws, bv, npm, 1.0f, nullptr, nullptr, vhT);

    // Fused attention (ctx out as fp16)
    attn_kernel<<<dim3(BB * HH, LL / 32), 512, ATT_SMEM>>>(
        qh, kh, vhT, mask, attn, ctx);

    // Output projection (ctx fp16 direct) -> fp32, then LN
    conv_f16<<<(nW4 + 255) / 256, 256>>>(Wf, ws, nW4);
    gemm_f16_1t<<<gG, 512, GEMM1_SMEM>>>(ctx, ws, bf, npm, 1.0f, proj, nullptr, nullptr);

    ln_kernel<<<ROWS_TOT, 256>>>(proj, q, ln_g, ln_b, out);
}